// round 1
// baseline (speedup 1.0000x reference)
#include <cuda_runtime.h>
#include <cstdint>

#define NNODES 50000
#define NEDGES 800000
#define NGRAPH 256
#define INC    128
#define HID    256

// Scratch (static device globals: allocation-free per harness rules)
static __device__ __align__(16) float g_z[(size_t)NNODES * HID];
static __device__ __align__(16) float g_t[(size_t)NNODES * HID];
static __device__ __align__(16) float g_h[(size_t)NNODES * HID];
// g_flags[0]: edge_index odd-word OR (0 => int64), g_flags[1]: batch odd-word OR
static __device__ unsigned g_flags[2];

__device__ __forceinline__ int ld_idx(const void* p, long long i, bool is64) {
    if (is64) return (int)__ldg(&((const long long*)p)[i]);
    return __ldg(&((const int*)p)[i]);
}

// Zero output + flags
__global__ void k_init(float* __restrict__ out) {
    int tid = blockIdx.x * blockDim.x + threadIdx.x;
    if (tid < 2) g_flags[tid] = 0u;
    for (int i = tid; i < NGRAPH * HID; i += gridDim.x * blockDim.x) out[i] = 0.f;
}

// Detect index dtype: for int64 non-negative small values, every odd 32-bit word is 0.
__global__ void k_detect(const unsigned* __restrict__ ei, const unsigned* __restrict__ ba) {
    long long stride = (long long)gridDim.x * blockDim.x;
    long long tid = (long long)blockIdx.x * blockDim.x + threadIdx.x;
    unsigned acc = 0;
    for (long long w = 2 * tid + 1; w < 2LL * NEDGES; w += 2 * stride) acc |= ei[w];
    if (acc) atomicOr(&g_flags[0], 1u);
    acc = 0;
    for (long long w = 2 * tid + 1; w < NNODES; w += 2 * stride) acc |= ba[w];
    if (acc) atomicOr(&g_flags[1], 1u);
}

__global__ void k_copy4(const float4* __restrict__ src, float4* __restrict__ dst, long long n4) {
    long long stride = (long long)gridDim.x * blockDim.x;
    for (long long i = (long long)blockIdx.x * blockDim.x + threadIdx.x; i < n4; i += stride)
        dst[i] = src[i];
}

// z[dst] += h[src] over all edges; one float4 column-group per thread.
// Hc = 4 << lg  (lg = 5 for Hc=128, lg = 6 for Hc=256)
__global__ void k_scatter(const float* __restrict__ h, float* __restrict__ z,
                          const void* __restrict__ ei, int lg) {
    bool is64 = (g_flags[0] == 0u);
    long long total = (long long)NEDGES << lg;
    long long stride = (long long)gridDim.x * blockDim.x;
    long long mask = (1LL << lg) - 1;
    for (long long t = (long long)blockIdx.x * blockDim.x + threadIdx.x; t < total; t += stride) {
        long long e = t >> lg;
        int c = (int)(t & mask) * 4;
        int s = ld_idx(ei, e, is64);
        int d = ld_idx(ei, (long long)NEDGES + e, is64);
        const float4 v = *(const float4*)(h + ((long long)s << (lg + 2)) + c);
        float* dp = z + ((long long)d << (lg + 2)) + c;
        asm volatile("red.global.add.v4.f32 [%0], {%1,%2,%3,%4};"
                     :: "l"(dp), "f"(v.x), "f"(v.y), "f"(v.z), "f"(v.w) : "memory");
    }
}

// C = relu(A[M,K] @ B[K,256] + bias), BM=128, BN=128, BK=16, 256 threads, TM=TN=8
__global__ void __launch_bounds__(256, 2)
k_gemm_relu(const float* __restrict__ A, const float* __restrict__ B,
            const float* __restrict__ bias, float* __restrict__ C, int K) {
    __shared__ float As[16][128];
    __shared__ float Bs[16][128];
    const int M = NNODES;
    int row0 = blockIdx.x * 128;
    int col0 = blockIdx.y * 128;
    int tid = threadIdx.x;
    int tm0 = (tid >> 4) * 8;
    int tn0 = (tid & 15) * 8;
    float acc[8][8];
#pragma unroll
    for (int m = 0; m < 8; m++)
#pragma unroll
        for (int n = 0; n < 8; n++) acc[m][n] = 0.f;

    for (int kt = 0; kt < K; kt += 16) {
#pragma unroll
        for (int i = 0; i < 2; i++) {
            int idx = tid * 2 + i;            // 0..511
            int r = idx >> 2, q = idx & 3;    // row in tile, quad of 4 floats
            int grow = row0 + r;
            float4 v = make_float4(0.f, 0.f, 0.f, 0.f);
            if (grow < M) v = *(const float4*)(A + (long long)grow * K + kt + q * 4);
            As[q * 4 + 0][r] = v.x; As[q * 4 + 1][r] = v.y;
            As[q * 4 + 2][r] = v.z; As[q * 4 + 3][r] = v.w;
        }
#pragma unroll
        for (int i = 0; i < 2; i++) {
            int idx = tid * 2 + i;
            int kr = idx >> 5, q = idx & 31;
            *(float4*)&Bs[kr][q * 4] =
                *(const float4*)(B + (long long)(kt + kr) * HID + col0 + q * 4);
        }
        __syncthreads();
#pragma unroll
        for (int k = 0; k < 16; k++) {
            float a[8], b[8];
            *(float4*)&a[0] = *(const float4*)&As[k][tm0];
            *(float4*)&a[4] = *(const float4*)&As[k][tm0 + 4];
            *(float4*)&b[0] = *(const float4*)&Bs[k][tn0];
            *(float4*)&b[4] = *(const float4*)&Bs[k][tn0 + 4];
#pragma unroll
            for (int m = 0; m < 8; m++)
#pragma unroll
                for (int n = 0; n < 8; n++)
                    acc[m][n] = fmaf(a[m], b[n], acc[m][n]);
        }
        __syncthreads();
    }

    float bv[8];
#pragma unroll
    for (int n = 0; n < 8; n++) bv[n] = bias[col0 + tn0 + n];
#pragma unroll
    for (int m = 0; m < 8; m++) {
        int grow = row0 + tm0 + m;
        if (grow < M) {
            float4 o0, o1;
            o0.x = fmaxf(acc[m][0] + bv[0], 0.f);
            o0.y = fmaxf(acc[m][1] + bv[1], 0.f);
            o0.z = fmaxf(acc[m][2] + bv[2], 0.f);
            o0.w = fmaxf(acc[m][3] + bv[3], 0.f);
            o1.x = fmaxf(acc[m][4] + bv[4], 0.f);
            o1.y = fmaxf(acc[m][5] + bv[5], 0.f);
            o1.z = fmaxf(acc[m][6] + bv[6], 0.f);
            o1.w = fmaxf(acc[m][7] + bv[7], 0.f);
            *(float4*)(C + (long long)grow * HID + col0 + tn0)     = o0;
            *(float4*)(C + (long long)grow * HID + col0 + tn0 + 4) = o1;
        }
    }
}

// out[batch[i]] += h[i]
__global__ void k_pool(const float* __restrict__ h, const void* __restrict__ ba,
                       float* __restrict__ out) {
    bool is64 = (g_flags[1] == 0u);
    long long total = (long long)NNODES * (HID / 4);
    long long stride = (long long)gridDim.x * blockDim.x;
    for (long long t = (long long)blockIdx.x * blockDim.x + threadIdx.x; t < total; t += stride) {
        long long i = t >> 6;
        int c = (int)(t & 63) * 4;
        int g = ld_idx(ba, i, is64);
        const float4 v = *(const float4*)(h + i * HID + c);
        float* dp = out + (long long)g * HID + c;
        asm volatile("red.global.add.v4.f32 [%0], {%1,%2,%3,%4};"
                     :: "l"(dp), "f"(v.x), "f"(v.y), "f"(v.z), "f"(v.w) : "memory");
    }
}

extern "C" void kernel_launch(void* const* d_in, const int* in_sizes, int n_in,
                              void* d_out, int out_size) {
    const float* x    = (const float*)d_in[0];
    const void*  ei   = d_in[1];
    const void*  ba   = d_in[2];
    const float* w1_0 = (const float*)d_in[3];
    const float* b1_0 = (const float*)d_in[4];
    const float* w2_0 = (const float*)d_in[5];
    const float* b2_0 = (const float*)d_in[6];
    const float* w1s  = (const float*)d_in[7];
    const float* b1s  = (const float*)d_in[8];
    const float* w2s  = (const float*)d_in[9];
    const float* b2s  = (const float*)d_in[10];
    float* out = (float*)d_out;

    float *z, *t, *h;
    cudaGetSymbolAddress((void**)&z, g_z);
    cudaGetSymbolAddress((void**)&t, g_t);
    cudaGetSymbolAddress((void**)&h, g_h);

    k_init<<<64, 256>>>(out);
    k_detect<<<256, 256>>>((const unsigned*)ei, (const unsigned*)ba);

    dim3 ggrid(391, 2);  // 391*128 = 50048 rows, 2 col-blocks of 128

    // Layer 0 (K = 128)
    k_copy4<<<2048, 256>>>((const float4*)x, (float4*)z, (long long)NNODES * INC / 4);
    k_scatter<<<4736, 256>>>(x, z, ei, 5);
    k_gemm_relu<<<ggrid, 256>>>(z, w1_0, b1_0, t, INC);
    k_gemm_relu<<<ggrid, 256>>>(t, w2_0, b2_0, h, HID);

    // Layers 1..3 (K = 256)
    for (int l = 0; l < 3; l++) {
        k_copy4<<<2048, 256>>>((const float4*)h, (float4*)z, (long long)NNODES * HID / 4);
        k_scatter<<<4736, 256>>>(h, z, ei, 6);
        k_gemm_relu<<<ggrid, 256>>>(z, w1s + (long long)l * HID * HID, b1s + l * HID, t, HID);
        k_gemm_relu<<<ggrid, 256>>>(t, w2s + (long long)l * HID * HID, b2s + l * HID, h, HID);
    }

    k_pool<<<2048, 256>>>(h, ba, out);
}

// round 2
// speedup vs baseline: 1.0065x; 1.0065x over previous
#include <cuda_runtime.h>
#include <cstdint>

#define NNODES 50000
#define NEDGES 800000
#define NGRAPH 256
#define INC    128
#define HID    256

// Scratch (static device globals: allocation-free per harness rules)
static __device__ __align__(16) float g_z[(size_t)NNODES * HID];
static __device__ __align__(16) float g_t[(size_t)NNODES * HID];
static __device__ __align__(16) float g_h[(size_t)NNODES * HID];
// g_flags[0]: edge_index odd-word OR (0 => int64), g_flags[1]: batch odd-word OR
static __device__ unsigned g_flags[2];

__device__ __forceinline__ int ld_idx(const void* p, long long i, bool is64) {
    if (is64) return (int)__ldg(&((const long long*)p)[i]);
    return __ldg(&((const int*)p)[i]);
}

// ---- packed f32x2 helpers (FFMA2: one instr = 2 fp32 FMAs) ----
__device__ __forceinline__ unsigned long long pack2(float lo, float hi) {
    unsigned long long r;
    asm("mov.b64 %0, {%1,%2};" : "=l"(r) : "f"(lo), "f"(hi));
    return r;
}
__device__ __forceinline__ void unpack2(unsigned long long v, float& lo, float& hi) {
    asm("mov.b64 {%0,%1}, %2;" : "=f"(lo), "=f"(hi) : "l"(v));
}
__device__ __forceinline__ void fma2(unsigned long long& d,
                                     unsigned long long a, unsigned long long b) {
    asm("fma.rn.f32x2 %0, %1, %2, %0;" : "+l"(d) : "l"(a), "l"(b));
}

// Zero output + flags
__global__ void k_init(float* __restrict__ out) {
    int tid = blockIdx.x * blockDim.x + threadIdx.x;
    if (tid < 2) g_flags[tid] = 0u;
    for (int i = tid; i < NGRAPH * HID; i += gridDim.x * blockDim.x) out[i] = 0.f;
}

// Detect index dtype: for int64 non-negative small values, every odd 32-bit word is 0.
__global__ void k_detect(const unsigned* __restrict__ ei, const unsigned* __restrict__ ba) {
    long long stride = (long long)gridDim.x * blockDim.x;
    long long tid = (long long)blockIdx.x * blockDim.x + threadIdx.x;
    unsigned acc = 0;
    for (long long w = 2 * tid + 1; w < 2LL * NEDGES; w += 2 * stride) acc |= ei[w];
    if (acc) atomicOr(&g_flags[0], 1u);
    acc = 0;
    for (long long w = 2 * tid + 1; w < NNODES; w += 2 * stride) acc |= ba[w];
    if (acc) atomicOr(&g_flags[1], 1u);
}

__global__ void k_copy4(const float4* __restrict__ src, float4* __restrict__ dst, long long n4) {
    long long stride = (long long)gridDim.x * blockDim.x;
    for (long long i = (long long)blockIdx.x * blockDim.x + threadIdx.x; i < n4; i += stride)
        dst[i] = src[i];
}

// z[dst] += h[src] over all edges; one float4 column-group per thread.
// Hc = 4 << lg  (lg = 5 for Hc=128, lg = 6 for Hc=256)
__global__ void k_scatter(const float* __restrict__ h, float* __restrict__ z,
                          const void* __restrict__ ei, int lg) {
    bool is64 = (g_flags[0] == 0u);
    long long total = (long long)NEDGES << lg;
    long long stride = (long long)gridDim.x * blockDim.x;
    long long mask = (1LL << lg) - 1;
    for (long long t = (long long)blockIdx.x * blockDim.x + threadIdx.x; t < total; t += stride) {
        long long e = t >> lg;
        int c = (int)(t & mask) * 4;
        int s = ld_idx(ei, e, is64);
        int d = ld_idx(ei, (long long)NEDGES + e, is64);
        const float4 v = *(const float4*)(h + ((long long)s << (lg + 2)) + c);
        float* dp = z + ((long long)d << (lg + 2)) + c;
        asm volatile("red.global.add.v4.f32 [%0], {%1,%2,%3,%4};"
                     :: "l"(dp), "f"(v.x), "f"(v.y), "f"(v.z), "f"(v.w) : "memory");
    }
}

// C = relu(A[M,K] @ B[K,256] + bias), BM=128, BN=128, BK=16, 256 threads, TM=TN=8
// Inner product in packed f32x2: M-dim paired (As is m-contiguous -> float2 loads),
// B broadcast via mov.b64 pack. 32 FFMA2 + 8 MOV per k instead of 64 FFMA.
__global__ void __launch_bounds__(256, 2)
k_gemm_relu(const float* __restrict__ A, const float* __restrict__ B,
            const float* __restrict__ bias, float* __restrict__ C, int K) {
    __shared__ float As[16][128];
    __shared__ float Bs[16][128];
    const int M = NNODES;
    int row0 = blockIdx.x * 128;
    int col0 = blockIdx.y * 128;
    int tid = threadIdx.x;
    int tm0 = (tid >> 4) * 8;
    int tn0 = (tid & 15) * 8;

    // acc2[m2][n]: m2 indexes pairs (2 rows packed in one 64-bit reg), n = 0..7
    unsigned long long acc2[4][8];
#pragma unroll
    for (int m = 0; m < 4; m++)
#pragma unroll
        for (int n = 0; n < 8; n++) acc2[m][n] = 0ull;

    for (int kt = 0; kt < K; kt += 16) {
#pragma unroll
        for (int i = 0; i < 2; i++) {
            int idx = tid * 2 + i;            // 0..511
            int r = idx >> 2, q = idx & 3;    // row in tile, quad of 4 floats
            int grow = row0 + r;
            float4 v = make_float4(0.f, 0.f, 0.f, 0.f);
            if (grow < M) v = *(const float4*)(A + (long long)grow * K + kt + q * 4);
            As[q * 4 + 0][r] = v.x; As[q * 4 + 1][r] = v.y;
            As[q * 4 + 2][r] = v.z; As[q * 4 + 3][r] = v.w;
        }
#pragma unroll
        for (int i = 0; i < 2; i++) {
            int idx = tid * 2 + i;
            int kr = idx >> 5, q = idx & 31;
            *(float4*)&Bs[kr][q * 4] =
                *(const float4*)(B + (long long)(kt + kr) * HID + col0 + q * 4);
        }
        __syncthreads();
#pragma unroll
        for (int k = 0; k < 16; k++) {
            // a: 4 packed pairs along m (directly from m-contiguous smem)
            unsigned long long a2[4];
            *(uint4*)&a2[0] = *(const uint4*)&As[k][tm0];       // a2[0],a2[1]
            *(uint4*)&a2[2] = *(const uint4*)&As[k][tm0 + 4];   // a2[2],a2[3]
            // b: 8 scalars, each broadcast-packed {b,b}
            float b[8];
            *(float4*)&b[0] = *(const float4*)&Bs[k][tn0];
            *(float4*)&b[4] = *(const float4*)&Bs[k][tn0 + 4];
            unsigned long long b2[8];
#pragma unroll
            for (int n = 0; n < 8; n++) b2[n] = pack2(b[n], b[n]);
#pragma unroll
            for (int m = 0; m < 4; m++)
#pragma unroll
                for (int n = 0; n < 8; n++)
                    fma2(acc2[m][n], a2[m], b2[n]);
        }
        __syncthreads();
    }

    float bv[8];
#pragma unroll
    for (int n = 0; n < 8; n++) bv[n] = bias[col0 + tn0 + n];
#pragma unroll
    for (int m2 = 0; m2 < 4; m2++) {
        float r0[8], r1[8];
#pragma unroll
        for (int n = 0; n < 8; n++) unpack2(acc2[m2][n], r0[n], r1[n]);
        int grow0 = row0 + tm0 + 2 * m2;
#pragma unroll
        for (int half = 0; half < 2; half++) {
            int grow = grow0 + half;
            if (grow < M) {
                const float* r = half ? r1 : r0;
                float4 o0, o1;
                o0.x = fmaxf(r[0] + bv[0], 0.f);
                o0.y = fmaxf(r[1] + bv[1], 0.f);
                o0.z = fmaxf(r[2] + bv[2], 0.f);
                o0.w = fmaxf(r[3] + bv[3], 0.f);
                o1.x = fmaxf(r[4] + bv[4], 0.f);
                o1.y = fmaxf(r[5] + bv[5], 0.f);
                o1.z = fmaxf(r[6] + bv[6], 0.f);
                o1.w = fmaxf(r[7] + bv[7], 0.f);
                *(float4*)(C + (long long)grow * HID + col0 + tn0)     = o0;
                *(float4*)(C + (long long)grow * HID + col0 + tn0 + 4) = o1;
            }
        }
    }
}

// out[batch[i]] += h[i]
__global__ void k_pool(const float* __restrict__ h, const void* __restrict__ ba,
                       float* __restrict__ out) {
    bool is64 = (g_flags[1] == 0u);
    long long total = (long long)NNODES * (HID / 4);
    long long stride = (long long)gridDim.x * blockDim.x;
    for (long long t = (long long)blockIdx.x * blockDim.x + threadIdx.x; t < total; t += stride) {
        long long i = t >> 6;
        int c = (int)(t & 63) * 4;
        int g = ld_idx(ba, i, is64);
        const float4 v = *(const float4*)(h + i * HID + c);
        float* dp = out + (long long)g * HID + c;
        asm volatile("red.global.add.v4.f32 [%0], {%1,%2,%3,%4};"
                     :: "l"(dp), "f"(v.x), "f"(v.y), "f"(v.z), "f"(v.w) : "memory");
    }
}

extern "C" void kernel_launch(void* const* d_in, const int* in_sizes, int n_in,
                              void* d_out, int out_size) {
    const float* x    = (const float*)d_in[0];
    const void*  ei   = d_in[1];
    const void*  ba   = d_in[2];
    const float* w1_0 = (const float*)d_in[3];
    const float* b1_0 = (const float*)d_in[4];
    const float* w2_0 = (const float*)d_in[5];
    const float* b2_0 = (const float*)d_in[6];
    const float* w1s  = (const float*)d_in[7];
    const float* b1s  = (const float*)d_in[8];
    const float* w2s  = (const float*)d_in[9];
    const float* b2s  = (const float*)d_in[10];
    float* out = (float*)d_out;

    float *z, *t, *h;
    cudaGetSymbolAddress((void**)&z, g_z);
    cudaGetSymbolAddress((void**)&t, g_t);
    cudaGetSymbolAddress((void**)&h, g_h);

    k_init<<<64, 256>>>(out);
    k_detect<<<256, 256>>>((const unsigned*)ei, (const unsigned*)ba);

    dim3 ggrid(391, 2);  // 391*128 = 50048 rows, 2 col-blocks of 128

    // Layer 0 (K = 128)
    k_copy4<<<2048, 256>>>((const float4*)x, (float4*)z, (long long)NNODES * INC / 4);
    k_scatter<<<4736, 256>>>(x, z, ei, 5);
    k_gemm_relu<<<ggrid, 256>>>(z, w1_0, b1_0, t, INC);
    k_gemm_relu<<<ggrid, 256>>>(t, w2_0, b2_0, h, HID);

    // Layers 1..3 (K = 256)
    for (int l = 0; l < 3; l++) {
        k_copy4<<<2048, 256>>>((const float4*)h, (float4*)z, (long long)NNODES * HID / 4);
        k_scatter<<<4736, 256>>>(h, z, ei, 6);
        k_gemm_relu<<<ggrid, 256>>>(z, w1s + (long long)l * HID * HID, b1s + l * HID, t, HID);
        k_gemm_relu<<<ggrid, 256>>>(t, w2s + (long long)l * HID * HID, b2s + l * HID, h, HID);
    }

    k_pool<<<2048, 256>>>(h, ba, out);
}

// round 3
// speedup vs baseline: 1.7197x; 1.7087x over previous
#include <cuda_runtime.h>
#include <cuda_bf16.h>
#include <cstdint>

#define NNODES 50000
#define NEDGES 800000
#define NGRAPH 256
#define INC    128
#define HID    256

#define BM 128
#define BN 128
#define BK 32
#define SA 40    // A smem row stride (bf16 elems): BK + 8
#define SB 136   // B smem row stride: BN + 8

// Scratch (static device globals: allocation-free per harness rules)
static __device__ __align__(16) float g_z[(size_t)NNODES * HID];
static __device__ __align__(16) float g_t[(size_t)NNODES * HID];
static __device__ __align__(16) float g_h[(size_t)NNODES * HID];
static __device__ unsigned g_flags[2];

__device__ __forceinline__ int ld_idx(const void* p, long long i, bool is64) {
    if (is64) return (int)__ldg(&((const long long*)p)[i]);
    return __ldg(&((const int*)p)[i]);
}

// Pack 2 floats -> bf16x2 (lo = x0), and residual bf16x2
__device__ __forceinline__ void cvt_hilo(float x0, float x1, unsigned& hi, unsigned& lo) {
    unsigned h;
    asm("cvt.rn.bf16x2.f32 %0, %1, %2;" : "=r"(h) : "f"(x1), "f"(x0));
    float f0 = __uint_as_float(h << 16);
    float f1 = __uint_as_float(h & 0xffff0000u);
    float r0 = x0 - f0, r1 = x1 - f1;
    unsigned l;
    asm("cvt.rn.bf16x2.f32 %0, %1, %2;" : "=r"(l) : "f"(r1), "f"(r0));
    hi = h; lo = l;
}

__global__ void k_init(float* __restrict__ out) {
    int tid = blockIdx.x * blockDim.x + threadIdx.x;
    if (tid < 2) g_flags[tid] = 0u;
    for (int i = tid; i < NGRAPH * HID; i += gridDim.x * blockDim.x) out[i] = 0.f;
}

__global__ void k_detect(const unsigned* __restrict__ ei, const unsigned* __restrict__ ba) {
    long long stride = (long long)gridDim.x * blockDim.x;
    long long tid = (long long)blockIdx.x * blockDim.x + threadIdx.x;
    unsigned acc = 0;
    for (long long w = 2 * tid + 1; w < 2LL * NEDGES; w += 2 * stride) acc |= ei[w];
    if (acc) atomicOr(&g_flags[0], 1u);
    acc = 0;
    for (long long w = 2 * tid + 1; w < NNODES; w += 2 * stride) acc |= ba[w];
    if (acc) atomicOr(&g_flags[1], 1u);
}

__global__ void k_copy4(const float4* __restrict__ src, float4* __restrict__ dst, long long n4) {
    long long stride = (long long)gridDim.x * blockDim.x;
    for (long long i = (long long)blockIdx.x * blockDim.x + threadIdx.x; i < n4; i += stride)
        dst[i] = src[i];
}

__global__ void k_scatter(const float* __restrict__ h, float* __restrict__ z,
                          const void* __restrict__ ei, int lg) {
    bool is64 = (g_flags[0] == 0u);
    long long total = (long long)NEDGES << lg;
    long long stride = (long long)gridDim.x * blockDim.x;
    long long mask = (1LL << lg) - 1;
    for (long long t = (long long)blockIdx.x * blockDim.x + threadIdx.x; t < total; t += stride) {
        long long e = t >> lg;
        int c = (int)(t & mask) * 4;
        int s = ld_idx(ei, e, is64);
        int d = ld_idx(ei, (long long)NEDGES + e, is64);
        const float4 v = *(const float4*)(h + ((long long)s << (lg + 2)) + c);
        float* dp = z + ((long long)d << (lg + 2)) + c;
        asm volatile("red.global.add.v4.f32 [%0], {%1,%2,%3,%4};"
                     :: "l"(dp), "f"(v.x), "f"(v.y), "f"(v.z), "f"(v.w) : "memory");
    }
}

// C = relu(A[M,K]@B[K,256] + bias) via bf16x3 split on tensor cores.
// BM=128,BN=128,BK=32; 8 warps as 2(M)x4(N); warp tile 64x32;
// mma.m16n8k16: mt=4, nt=4, kc=2, 3 precision combos.
__global__ void __launch_bounds__(256)
k_gemm_bf16x3(const float* __restrict__ A, const float* __restrict__ B,
              const float* __restrict__ bias, float* __restrict__ C, int K) {
    __shared__ __align__(16) unsigned short Ah[BM * SA];
    __shared__ __align__(16) unsigned short Al[BM * SA];
    __shared__ __align__(16) unsigned short Bh[BK * SB];
    __shared__ __align__(16) unsigned short Bl[BK * SB];

    const int M = NNODES;
    int tid = threadIdx.x;
    int lane = tid & 31;
    int warp = tid >> 5;
    int wm = (warp & 1) * 64;
    int wn = (warp >> 1) * 32;
    int row0 = blockIdx.x * BM;
    int col0 = blockIdx.y * BN;

    float c[4][4][4];
#pragma unroll
    for (int mt = 0; mt < 4; mt++)
#pragma unroll
        for (int nt = 0; nt < 4; nt++)
#pragma unroll
            for (int i = 0; i < 4; i++) c[mt][nt][i] = 0.f;

    for (int kt = 0; kt < K; kt += BK) {
        // Stage A tile (128x32 fp32) -> bf16 hi/lo
#pragma unroll
        for (int i = 0; i < 4; i++) {
            int lin = tid + i * 256;
            int r = lin >> 3, q = lin & 7;
            int gr = row0 + r;
            float4 v = make_float4(0.f, 0.f, 0.f, 0.f);
            if (gr < M) v = *(const float4*)(A + (long long)gr * K + kt + q * 4);
            unsigned h0, l0, h1, l1;
            cvt_hilo(v.x, v.y, h0, l0);
            cvt_hilo(v.z, v.w, h1, l1);
            *(uint2*)&Ah[r * SA + q * 4] = make_uint2(h0, h1);
            *(uint2*)&Al[r * SA + q * 4] = make_uint2(l0, l1);
        }
        // Stage B tile (32x128 fp32) -> bf16 hi/lo
#pragma unroll
        for (int i = 0; i < 4; i++) {
            int lin = tid + i * 256;
            int r = lin >> 5, q = lin & 31;
            float4 v = *(const float4*)(B + (long long)(kt + r) * HID + col0 + q * 4);
            unsigned h0, l0, h1, l1;
            cvt_hilo(v.x, v.y, h0, l0);
            cvt_hilo(v.z, v.w, h1, l1);
            *(uint2*)&Bh[r * SB + q * 4] = make_uint2(h0, h1);
            *(uint2*)&Bl[r * SB + q * 4] = make_uint2(l0, l1);
        }
        __syncthreads();

#pragma unroll
        for (int kc = 0; kc < 2; kc++) {
            unsigned ah[4][4], al[4][4], bh[4][2], bl[4][2];
            int arow = lane & 15;
            int acol = kc * 16 + (lane >> 4) * 8;
#pragma unroll
            for (int mt = 0; mt < 4; mt++) {
                unsigned sa = (unsigned)__cvta_generic_to_shared(
                    &Ah[(wm + mt * 16 + arow) * SA + acol]);
                asm volatile("ldmatrix.sync.aligned.m8n8.x4.shared.b16 {%0,%1,%2,%3}, [%4];"
                             : "=r"(ah[mt][0]), "=r"(ah[mt][1]), "=r"(ah[mt][2]), "=r"(ah[mt][3])
                             : "r"(sa));
                unsigned sb = (unsigned)__cvta_generic_to_shared(
                    &Al[(wm + mt * 16 + arow) * SA + acol]);
                asm volatile("ldmatrix.sync.aligned.m8n8.x4.shared.b16 {%0,%1,%2,%3}, [%4];"
                             : "=r"(al[mt][0]), "=r"(al[mt][1]), "=r"(al[mt][2]), "=r"(al[mt][3])
                             : "r"(sb));
            }
            int brow = kc * 16 + (lane & 15);
#pragma unroll
            for (int nt2 = 0; nt2 < 2; nt2++) {
                int bcol = wn + nt2 * 16 + (lane >> 4) * 8;
                unsigned sh = (unsigned)__cvta_generic_to_shared(&Bh[brow * SB + bcol]);
                asm volatile("ldmatrix.sync.aligned.m8n8.x4.trans.shared.b16 {%0,%1,%2,%3}, [%4];"
                             : "=r"(bh[2 * nt2][0]), "=r"(bh[2 * nt2][1]),
                               "=r"(bh[2 * nt2 + 1][0]), "=r"(bh[2 * nt2 + 1][1])
                             : "r"(sh));
                unsigned sl = (unsigned)__cvta_generic_to_shared(&Bl[brow * SB + bcol]);
                asm volatile("ldmatrix.sync.aligned.m8n8.x4.trans.shared.b16 {%0,%1,%2,%3}, [%4];"
                             : "=r"(bl[2 * nt2][0]), "=r"(bl[2 * nt2][1]),
                               "=r"(bl[2 * nt2 + 1][0]), "=r"(bl[2 * nt2 + 1][1])
                             : "r"(sl));
            }
#pragma unroll
            for (int mt = 0; mt < 4; mt++)
#pragma unroll
                for (int nt = 0; nt < 4; nt++) {
                    float* cc = c[mt][nt];
#define MMA(AREG, BREG)                                                              \
    asm volatile("mma.sync.aligned.m16n8k16.row.col.f32.bf16.bf16.f32 "              \
                 "{%0,%1,%2,%3}, {%4,%5,%6,%7}, {%8,%9}, {%0,%1,%2,%3};"             \
                 : "+f"(cc[0]), "+f"(cc[1]), "+f"(cc[2]), "+f"(cc[3])                \
                 : "r"(AREG[0]), "r"(AREG[1]), "r"(AREG[2]), "r"(AREG[3]),           \
                   "r"(BREG[0]), "r"(BREG[1]))
                    MMA(ah[mt], bh[nt]);
                    MMA(ah[mt], bl[nt]);
                    MMA(al[mt], bh[nt]);
#undef MMA
                }
        }
        __syncthreads();
    }

    // Epilogue: relu(c + bias)
    int g = lane >> 2, tg = lane & 3;
#pragma unroll
    for (int nt = 0; nt < 4; nt++) {
        int gcol = col0 + wn + nt * 8 + tg * 2;
        float b0 = bias[gcol], b1 = bias[gcol + 1];
#pragma unroll
        for (int mt = 0; mt < 4; mt++) {
            int r0 = row0 + wm + mt * 16 + g;
            int r1 = r0 + 8;
            if (r0 < M) {
                float2 o;
                o.x = fmaxf(c[mt][nt][0] + b0, 0.f);
                o.y = fmaxf(c[mt][nt][1] + b1, 0.f);
                *(float2*)(C + (long long)r0 * HID + gcol) = o;
            }
            if (r1 < M) {
                float2 o;
                o.x = fmaxf(c[mt][nt][2] + b0, 0.f);
                o.y = fmaxf(c[mt][nt][3] + b1, 0.f);
                *(float2*)(C + (long long)r1 * HID + gcol) = o;
            }
        }
    }
}

__global__ void k_pool(const float* __restrict__ h, const void* __restrict__ ba,
                       float* __restrict__ out) {
    bool is64 = (g_flags[1] == 0u);
    long long total = (long long)NNODES * (HID / 4);
    long long stride = (long long)gridDim.x * blockDim.x;
    for (long long t = (long long)blockIdx.x * blockDim.x + threadIdx.x; t < total; t += stride) {
        long long i = t >> 6;
        int c = (int)(t & 63) * 4;
        int g = ld_idx(ba, i, is64);
        const float4 v = *(const float4*)(h + i * HID + c);
        float* dp = out + (long long)g * HID + c;
        asm volatile("red.global.add.v4.f32 [%0], {%1,%2,%3,%4};"
                     :: "l"(dp), "f"(v.x), "f"(v.y), "f"(v.z), "f"(v.w) : "memory");
    }
}

extern "C" void kernel_launch(void* const* d_in, const int* in_sizes, int n_in,
                              void* d_out, int out_size) {
    const float* x    = (const float*)d_in[0];
    const void*  ei   = d_in[1];
    const void*  ba   = d_in[2];
    const float* w1_0 = (const float*)d_in[3];
    const float* b1_0 = (const float*)d_in[4];
    const float* w2_0 = (const float*)d_in[5];
    const float* b2_0 = (const float*)d_in[6];
    const float* w1s  = (const float*)d_in[7];
    const float* b1s  = (const float*)d_in[8];
    const float* w2s  = (const float*)d_in[9];
    const float* b2s  = (const float*)d_in[10];
    float* out = (float*)d_out;

    float *z, *t, *h;
    cudaGetSymbolAddress((void**)&z, g_z);
    cudaGetSymbolAddress((void**)&t, g_t);
    cudaGetSymbolAddress((void**)&h, g_h);

    k_init<<<64, 256>>>(out);
    k_detect<<<256, 256>>>((const unsigned*)ei, (const unsigned*)ba);

    dim3 ggrid((NNODES + BM - 1) / BM, HID / BN);  // (391, 2)

    // Layer 0 (K = 128)
    k_copy4<<<2048, 256>>>((const float4*)x, (float4*)z, (long long)NNODES * INC / 4);
    k_scatter<<<4736, 256>>>(x, z, ei, 5);
    k_gemm_bf16x3<<<ggrid, 256>>>(z, w1_0, b1_0, t, INC);
    k_gemm_bf16x3<<<ggrid, 256>>>(t, w2_0, b2_0, h, HID);

    // Layers 1..3 (K = 256)
    for (int l = 0; l < 3; l++) {
        k_copy4<<<2048, 256>>>((const float4*)h, (float4*)z, (long long)NNODES * HID / 4);
        k_scatter<<<4736, 256>>>(h, z, ei, 6);
        k_gemm_bf16x3<<<ggrid, 256>>>(z, w1s + (long long)l * HID * HID, b1s + l * HID, t, HID);
        k_gemm_bf16x3<<<ggrid, 256>>>(t, w2s + (long long)l * HID * HID, b2s + l * HID, h, HID);
    }

    k_pool<<<2048, 256>>>(h, ba, out);
}